// round 15
// baseline (speedup 1.0000x reference)
#include <cuda_runtime.h>
#include <cstdint>
#include <cstddef>

// ============================================================================
// AlignToZWignerD: D^l (l=0..4) Wigner blocks for real spherical harmonics,
// Ivanic-Ruedenberg recurrence, fully unrolled at compile time.
// Output (N, 25, 25) fp32, block-diagonal. N = 200000.
//
// Warp-specialized pipeline per CTA (64 threads):
//   warp 0 (producer): computes 32 points' compact D-blocks into buf[i&1]
//   warp 1 (consumer): streams batch i-1 from buf[(i-1)&1] to gmem
// Double-buffered, one __syncthreads per batch; persistent-style grid so the
// store warps keep DRAM busy ~95% of the time.
// ============================================================================

#define COMPACT 165       // 1 + 9 + 25 + 49 + 81
#define ROWSTRIDE 167     // pad: gcd(167,32)=1 -> conflict-free smem access
#define BATCH 32

// ---------------- compile-time sqrt (Newton, double) ----------------
constexpr __host__ __device__ double csqrt_(double x) {
    if (x <= 0.0) return 0.0;
    double r = x > 1.0 ? x : 1.0;
    for (int i = 0; i < 60; i++) r = 0.5 * (r + x / r);
    return r;
}

// ---------------- compile-time u, v, w coefficients ----------------
constexpr __host__ __device__ double denom_(int l, int mp) {
    return (mp == l || mp == -l) ? double((2 * l) * (2 * l - 1))
                                 : double((l + mp) * (l - mp));
}
constexpr __host__ __device__ double u_of(int l, int m, int mp) {
    return csqrt_(double((l + m) * (l - m)) / denom_(l, mp));
}
constexpr __host__ __device__ double v_of(int l, int m, int mp) {
    int am = m < 0 ? -m : m;
    double d0 = (m == 0) ? 1.0 : 0.0;
    return 0.5 * csqrt_((1.0 + d0) * double((l + am - 1) * (l + am)) / denom_(l, mp))
           * (1.0 - 2.0 * d0);
}
constexpr __host__ __device__ double w_of(int l, int m, int mp) {
    int am = m < 0 ? -m : m;
    double d0 = (m == 0) ? 1.0 : 0.0;
    int wn = l - am - 1; if (wn < 0) wn = 0;
    return -0.5 * csqrt_(double(wn * (l - am)) / denom_(l, mp)) * (1.0 - d0);
}

// ---------------- integer sequence (self-contained) ----------------
template <int... Is> struct ISeq {};
template <int N, int... Is> struct MkSeq : MkSeq<N - 1, N - 1, Is...> {};
template <int... Is> struct MkSeq<0, Is...> { using type = ISeq<Is...>; };

// ---------------- P term (all indices compile-time) ----------------
template <int L, int I, int A, int B>
__device__ __forceinline__ float Pt(const float (&r1)[9],
                                    const float (&dp)[(2 * L - 1) * (2 * L - 1)]) {
    constexpr int lp = L - 1, np = 2 * L - 1, row = (I + 1) * 3;
    if constexpr (B == L)
        return r1[row + 2] * dp[(A + lp) * np + 2 * lp]
             - r1[row + 0] * dp[(A + lp) * np + 0];
    else if constexpr (B == -L)
        return r1[row + 2] * dp[(A + lp) * np + 0]
             + r1[row + 0] * dp[(A + lp) * np + 2 * lp];
    else
        return r1[row + 1] * dp[(A + lp) * np + (B + lp)];
}

// ---------------- one D^L entry (coefficients are immediates) ----------------
template <int L, int M, int MP>
__device__ __forceinline__ float entry(const float (&r1)[9],
                                       const float (&dp)[(2 * L - 1) * (2 * L - 1)]) {
    constexpr float u = (float)u_of(L, M, MP);
    constexpr float v = (float)v_of(L, M, MP);
    constexpr float w = (float)w_of(L, M, MP);
    constexpr float SQ2 = 1.41421356237309515f;
    float acc = 0.0f;
    if constexpr (u != 0.0f)
        acc += u * Pt<L, 0, M, MP>(r1, dp);
    if constexpr (v != 0.0f) {
        if constexpr (M == 0) {
            acc += v * (Pt<L, 1, 1, MP>(r1, dp) + Pt<L, -1, -1, MP>(r1, dp));
        } else if constexpr (M > 0) {
            constexpr float s = (M == 1) ? SQ2 : 1.0f;
            acc += (v * s) * Pt<L, 1, M - 1, MP>(r1, dp);
            if constexpr (M != 1)
                acc -= v * Pt<L, -1, -M + 1, MP>(r1, dp);
        } else {
            if constexpr (M != -1)
                acc += v * Pt<L, 1, M + 1, MP>(r1, dp);
            constexpr float s = (M == -1) ? SQ2 : 1.0f;
            acc += (v * s) * Pt<L, -1, -M - 1, MP>(r1, dp);
        }
    }
    if constexpr (w != 0.0f) {
        if constexpr (M > 0)
            acc += w * (Pt<L, 1, M + 1, MP>(r1, dp) + Pt<L, -1, -M - 1, MP>(r1, dp));
        else
            acc += w * (Pt<L, 1, M - 1, MP>(r1, dp) - Pt<L, -1, -M + 1, MP>(r1, dp));
    }
    return acc;
}

// ---------------- build D^L into registers / into smem ----------------
template <int L, int... Is>
__device__ __forceinline__ void build_reg_impl(const float (&r1)[9],
                                               const float (&dp)[(2 * L - 1) * (2 * L - 1)],
                                               float (&dl)[(2 * L + 1) * (2 * L + 1)],
                                               ISeq<Is...>) {
    ((dl[Is] = entry<L, Is / (2 * L + 1) - L, Is % (2 * L + 1) - L>(r1, dp)), ...);
}
template <int L>
__device__ __forceinline__ void build_reg(const float (&r1)[9],
                                          const float (&dp)[(2 * L - 1) * (2 * L - 1)],
                                          float (&dl)[(2 * L + 1) * (2 * L + 1)]) {
    build_reg_impl<L>(r1, dp, dl, typename MkSeq<(2 * L + 1) * (2 * L + 1)>::type{});
}

template <int L, int... Is>
__device__ __forceinline__ void build_smem_impl(const float (&r1)[9],
                                                const float (&dp)[(2 * L - 1) * (2 * L - 1)],
                                                float* __restrict__ srow, ISeq<Is...>) {
    ((srow[Is] = entry<L, Is / (2 * L + 1) - L, Is % (2 * L + 1) - L>(r1, dp)), ...);
}
template <int L>
__device__ __forceinline__ void build_smem(const float (&r1)[9],
                                           const float (&dp)[(2 * L - 1) * (2 * L - 1)],
                                           float* __restrict__ srow) {
    build_smem_impl<L>(r1, dp, srow, typename MkSeq<(2 * L + 1) * (2 * L + 1)>::type{});
}

// ---------------- output map: 625 -> compact idx, pad -> -1 (zero) ----------
struct CmapT { short v[640]; };
constexpr __host__ __device__ CmapT make_cmap() {
    CmapT c{};
    for (int j = 0; j < 640; j++) c.v[j] = -1;        // zero marker
    for (int j = 0; j < 625; j++) {
        int r = j / 25, cc = j % 25;
        int l = 0;
        while ((l + 1) * (l + 1) <= r) l++;
        int lo = l * l, hi = (l + 1) * (l + 1);
        if (cc >= lo && cc < hi) {
            int base = l * (2 * l - 1) * (2 * l + 1) / 3;   // 0,1,10,35,84
            c.v[j] = (short)(base + (r - lo) * (2 * l + 1) + (cc - lo));
        }
    }
    return c;
}
__device__ const CmapT G_CMAP = make_cmap();

// ---------------- producer: compute one batch into a smem buffer ----------
__device__ __forceinline__ void compute_batch(const float* __restrict__ xyz,
                                              float* __restrict__ buf,
                                              int pbase, int lane, int N) {
    const int p = pbase + lane;
    float* row = buf + lane * ROWSTRIDE;
    if (p >= N) return;

    float x = xyz[3 * p + 0], y = xyz[3 * p + 1], z = xyz[3 * p + 2];
    float nrm = sqrtf(x * x + y * y + z * z);
    float inv = 1.0f / fmaxf(nrm, 1e-14f);
    float vx = x * inv, vy = y * inv, vz = z * inv;
    float ct = fminf(1.0f, fmaxf(-1.0f, vz));
    float st = sqrtf(fmaxf(0.0f, 1.0f - ct * ct));
    float rxy = sqrtf(vx * vx + vy * vy);
    float cp, sp;
    if (rxy > 0.0f) { float ir = 1.0f / rxy; cp = vx * ir; sp = vy * ir; }
    else            { cp = 1.0f; sp = 0.0f; }

    // D^1 in real-SH basis (rows/cols permuted by p=[1,2,0])
    float r1[9] = { cp,      0.0f, -sp,
                    st * sp, ct,    st * cp,
                    ct * sp, -st,   ct * cp };

    row[0] = 1.0f;
    #pragma unroll
    for (int i = 0; i < 9; i++) row[1 + i] = r1[i];

    float d2[25];
    build_reg<2>(r1, r1, d2);
    #pragma unroll
    for (int i = 0; i < 25; i++) row[10 + i] = d2[i];

    float d3[49];
    build_reg<3>(r1, d2, d3);
    #pragma unroll
    for (int i = 0; i < 49; i++) row[35 + i] = d3[i];

    build_smem<4>(r1, d3, row + 84);     // 81 entries straight to smem
}

// ---------------- consumer: stream one batch smem -> gmem ----------------
__device__ __forceinline__ void store_batch(const float* __restrict__ buf,
                                            float* __restrict__ out,
                                            int pbase, int lane, int N,
                                            const int (&mi)[20], unsigned nzmask) {
    float* o = out + (size_t)pbase * 625 + lane;
    const int npt = (pbase + BATCH <= N) ? BATCH : (N - pbase > 0 ? N - pbase : 0);

    #pragma unroll 2
    for (int pt = 0; pt < npt; pt++) {
        const float* r = buf + pt * ROWSTRIDE;
        #pragma unroll
        for (int it = 0; it < 20; it++) {
            int j = it * 32;
            if (j + lane < 625) {
                float v = 0.0f;
                if (nzmask & (1u << it)) v = r[mi[it]];   // predicated LDS
                __stcs(o + j, v);                          // streaming store
            }
        }
        o += 625;
    }
}

// ---------------- main kernel: 2 warps/CTA, double-buffered pipeline --------
__global__ void __launch_bounds__(64, 5)
AlignToZWignerD_kernel(const float* __restrict__ xyz, float* __restrict__ out, int N) {
    __shared__ float buf[2][BATCH * ROWSTRIDE];
    const int lane = threadIdx.x & 31;
    const int warp = threadIdx.x >> 5;

    const int nbatch = (N + BATCH - 1) / BATCH;
    const int stride = gridDim.x;
    // batches owned by this CTA: blockIdx.x, blockIdx.x + stride, ...
    const int K = (nbatch > (int)blockIdx.x)
                      ? (nbatch - (int)blockIdx.x + stride - 1) / stride : 0;

    // consumer hoists the output map + nonzero mask once
    int mi[20];
    unsigned nzmask = 0;
    if (warp == 1) {
        #pragma unroll
        for (int it = 0; it < 20; it++) {
            int j = it * 32 + lane;
            int m = (j < 625) ? (int)G_CMAP.v[j] : -1;
            mi[it] = (m >= 0) ? m : 0;
            if (m >= 0) nzmask |= (1u << it);
        }
    }

    for (int i = 0; i <= K; i++) {
        if (warp == 0 && i < K) {
            int b = blockIdx.x + i * stride;
            compute_batch(xyz, buf[i & 1], b * BATCH, lane, N);
            __syncwarp();
        }
        if (warp == 1 && i > 0) {
            int b = blockIdx.x + (i - 1) * stride;
            store_batch(buf[(i - 1) & 1], out, b * BATCH, lane, N, mi, nzmask);
        }
        __syncthreads();
    }
}

// ---------------- launch ----------------
extern "C" void kernel_launch(void* const* d_in, const int* in_sizes, int n_in,
                              void* d_out, int out_size) {
    const float* xyz = (const float*)d_in[0];
    float* out = (float*)d_out;
    int N = in_sizes[0] / 3;
    int nbatch = (N + BATCH - 1) / BATCH;
    int grid = 148 * 5;                 // 5 CTAs/SM, persistent-style
    if (grid > nbatch) grid = nbatch;
    AlignToZWignerD_kernel<<<grid, 64>>>(xyz, out, N);
}